// round 13
// baseline (speedup 1.0000x reference)
#include <cuda_runtime.h>

#define NA   9
#define NAA  81
#define HH   192
#define WWID 192
#define HW   (192*192)
#define CIN  32
#define MOUT 4
#define ND   9

typedef unsigned long long u64;

// scratch: mask pre-scaled by 81/sum (folds the mask_avg division)
__device__ float g_mask[NAA * HW];

__device__ __forceinline__ u64 fma2(u64 a, u64 b, u64 c) {
    u64 d; asm("fma.rn.f32x2 %0, %1, %2, %3;" : "=l"(d) : "l"(a), "l"(b), "l"(c)); return d;
}
__device__ __forceinline__ u64 mul2(u64 a, u64 b) {
    u64 d; asm("mul.rn.f32x2 %0, %1, %2;" : "=l"(d) : "l"(a), "l"(b)); return d;
}
__device__ __forceinline__ u64 pack2(float lo, float hi) {
    u64 d; asm("mov.b64 %0, {%1, %2};" : "=l"(d) : "f"(lo), "f"(hi)); return d;
}

__global__ void mask_scale_k(const float* __restrict__ mask) {
    int idx = blockIdx.x * 256 + threadIdx.x;
    if (idx >= HW) return;
    float s = 0.f;
    #pragma unroll 9
    for (int a = 0; a < NAA; a++) s += mask[a * HW + idx];
    float inv = 81.0f / s;
    #pragma unroll 9
    for (int a = 0; a < NAA; a++) g_mask[a * HW + idx] = mask[a * HW + idx] * inv;
}

// Fast (interior) path for one d-group G: dd = 3G..3G+2, d = dd-4.
// p,q,k fully unrolled; all offsets compile-time.
// __syncthreads() per p keeps the 3 co-resident d-groups tap-aligned so the
// per-p x footprint (~108KB) stays L1-resident across groups.
template <int G>
__device__ __forceinline__ void accumulate_fast(const float* __restrict__ xc,
                                                const float4* __restrict__ sWf,
                                                int base, u64 acc[3][4]) {
    const float* b0 = xc + base;
    const float* m0 = g_mask + base;
    #pragma unroll
    for (int p = 0; p < 9; p++) {
        __syncthreads();
        const int pp = 4 - p;
        #pragma unroll
        for (int q = 0; q < 9; q++) {
            const int qq = 4 - q;
            const int pq = p * 9 + q;
            float4 w = sWf[pq];                 // 1x LDS.128 broadcast
            u64 w0 = pack2(w.x, w.x);
            u64 w1 = pack2(w.y, w.y);
            u64 w2 = pack2(w.z, w.z);
            u64 w3 = pack2(w.w, w.w);
            u64 mask2 = *(const u64*)(m0 + pq * HW);
            #pragma unroll
            for (int k = 0; k < 3; k++) {
                const int d = 3 * G + k - 4;                       // compile-time
                const int off = pq * HW + d * (pp * WWID + qq);    // literal
                u64 x2;
                if (((qq & 1) == 0) || ((d & 1) == 0)) {
                    x2 = *(const u64*)(b0 + off);
                } else {
                    x2 = pack2(b0[off], b0[off + 1]);
                }
                u64 t2 = mul2(mask2, x2);
                acc[k][0] = fma2(w0, t2, acc[k][0]);
                acc[k][1] = fma2(w1, t2, acc[k][1]);
                acc[k][2] = fma2(w2, t2, acc[k][2]);
                acc[k][3] = fma2(w3, t2, acc[k][3]);
            }
        }
    }
}

// Boundary path for d-group G: rolled p-loop with full bounds checks.
// Same 9 per-p barrier arrivals as the fast path (uniform per CTA).
template <int G>
__device__ __forceinline__ void accumulate_chk(const float* __restrict__ xc,
                                               const float4* __restrict__ sWf,
                                               int i, int j, u64 acc[3][4]) {
    const int base = i * WWID + j;
    #pragma unroll 1
    for (int p = 0; p < 9; p++) {
        __syncthreads();
        const int pp = 4 - p;
        const int prow = pp * WWID;
        const float* bp = xc + base + p * 9 * HW;
        const float* mp = g_mask + base + p * 9 * HW;
        const float* bpd[3];
        int rowv[3];
        #pragma unroll
        for (int k = 0; k < 3; k++) {
            const int d = 3 * G + k - 4;
            bpd[k] = bp + d * prow;
            rowv[k] = i + d * pp;
        }
        #pragma unroll
        for (int q = 0; q < 9; q++) {
            const int qq = 4 - q;
            const int pq = p * 9 + q;
            float4 w = sWf[pq];
            u64 w0 = pack2(w.x, w.x);
            u64 w1 = pack2(w.y, w.y);
            u64 w2 = pack2(w.z, w.z);
            u64 w3 = pack2(w.w, w.w);
            u64 mask2 = *(const u64*)(mp + q * HW);
            #pragma unroll
            for (int k = 0; k < 3; k++) {
                const int d = 3 * G + k - 4;
                const int off = q * HW + d * qq;
                int colv = j + d * qq;
                bool rok = ((unsigned)rowv[k] < (unsigned)HH);
                u64 x2;
                if (((qq & 1) == 0) || ((d & 1) == 0)) {
                    bool ok = rok && ((unsigned)colv < (unsigned)(WWID - 1));
                    x2 = ok ? *(const u64*)(bpd[k] + off) : 0ull;
                } else {
                    float lo = (rok && (unsigned)colv       < (unsigned)WWID) ? bpd[k][off]     : 0.f;
                    float hi = (rok && (unsigned)(colv + 1) < (unsigned)WWID) ? bpd[k][off + 1] : 0.f;
                    x2 = pack2(lo, hi);
                }
                u64 t2 = mul2(mask2, x2);
                acc[k][0] = fma2(w0, t2, acc[k][0]);
                acc[k][1] = fma2(w1, t2, acc[k][1]);
                acc[k][2] = fma2(w2, t2, acc[k][2]);
                acc[k][3] = fma2(w3, t2, acc[k][3]);
            }
        }
    }
}

__global__ __launch_bounds__(768, 1)
void build_cost_k(const float* __restrict__ x,
                  const float* __restrict__ W,
                  float* __restrict__ out) {
    __shared__ __align__(16) float4 sWf[NAA];   // W[c*4+0..3][pq] as float4 per pq
    const int tx = threadIdx.x;          // 0..15  (pixel pair in j)
    const int ty = threadIdx.y;          // 0..15  (row)
    const int g  = threadIdx.z;          // 0..2   (d-group, shares L1 within CTA)
    const int tid = (g * 16 + ty) * 16 + tx;
    const int c = blockIdx.z;
    const int j0 = blockIdx.x * 32;
    const int i0 = blockIdx.y * 16;

    for (int t = tid; t < NAA * MOUT; t += 768) {
        int m = t & 3, pq = t >> 2;
        ((float*)sWf)[pq * 4 + m] = W[(c * MOUT + m) * NAA + pq];
    }
    __syncthreads();

    const int i = i0 + ty;
    const int j = j0 + tx * 2;

    u64 acc[3][4];
    #pragma unroll
    for (int k = 0; k < 3; k++)
        #pragma unroll
        for (int m = 0; m < 4; m++) acc[k][m] = 0ull;

    const float* xc = x + (size_t)c * NAA * HW;

    const bool interior = (i0 >= 16) && (i0 + 16 <= HH - 16) &&
                          (j0 >= 16) && (j0 + 32 <= WWID - 16);
    const int base = i * WWID + j;
    if (interior) {
        if (g == 0)      accumulate_fast<0>(xc, sWf, base, acc);
        else if (g == 1) accumulate_fast<1>(xc, sWf, base, acc);
        else             accumulate_fast<2>(xc, sWf, base, acc);
    } else {
        if (g == 0)      accumulate_chk<0>(xc, sWf, i, j, acc);
        else if (g == 1) accumulate_chk<1>(xc, sWf, i, j, acc);
        else             accumulate_chk<2>(xc, sWf, i, j, acc);
    }

    #pragma unroll
    for (int m = 0; m < 4; m++)
        #pragma unroll
        for (int k = 0; k < 3; k++) {
            int dd = 3 * g + k;
            *(u64*)(out + (size_t)((c * MOUT + m) * ND + dd) * HW + base) = acc[k][m];
        }
}

extern "C" void kernel_launch(void* const* d_in, const int* in_sizes, int n_in,
                              void* d_out, int out_size) {
    const float* x    = (const float*)d_in[0];  // [1,32,81,192,192]
    const float* mask = (const float*)d_in[1];  // [1,81,192,192]
    const float* W    = (const float*)d_in[2];  // [128,81]
    float* out = (float*)d_out;                 // [1,128,9,192,192]

    mask_scale_k<<<(HW + 255) / 256, 256>>>(mask);

    dim3 grid(WWID / 32, HH / 16, CIN);   // one CTA per (tile, c); 3 d-groups inside
    dim3 block(16, 16, 3);
    build_cost_k<<<grid, block>>>(x, W, out);
}